// round 4
// baseline (speedup 1.0000x reference)
#include <cuda_runtime.h>

#define HW    16384         // 128*128
#define HW2   8192          // float2 elements per channel
#define Bn    8
#define Cn    10
#define NPV   65536         // total float2 elements per channel-slice view (Bn*HW2)
#define NTH   128
#define NBL   512           // NBL*NTH = NPV

// Scratch (allocation-free: __device__ globals)
__device__ float g_part1[40 * NBL];     // per-block partials: ch 0..19 = sum, 20..39 = sumsq
__device__ float g_part2[20 * NBL];     // ch 0..9 = sum, 10..19 = sumsq
__device__ float g_p1[40];              // BN1 folded scale/shift
__device__ float g_p2[20];              // BN2 folded scale/shift
__device__ float g_t1[Bn*2*Cn*HW];      // conv1 pre-BN output [b,20,hw]
__device__ float g_y2[Bn*Cn*HW];        // conv2 pre-BN output [b,10,hw]

__device__ __forceinline__ float sigm(float x){ return 1.f/(1.f+__expf(-x)); }
__device__ __forceinline__ float ftanh(float x){ return fmaf(2.f, 1.f/(1.f+__expf(-2.f*x)), -1.f); }

// Pass A: node0 (ConvGRU on h0/f0), comp_att, t1 = W_r1 @ [f1,(h1+h2)*att], BN1 block partials
__global__ void __launch_bounds__(NTH) k_passA(
    const float* __restrict__ f0, const float* __restrict__ h0,
    const float* __restrict__ f1, const float* __restrict__ h1, const float* __restrict__ h2,
    const float* __restrict__ W_att, const float* __restrict__ b_att,
    const float* __restrict__ W_r1,
    const float* __restrict__ Wg0, const float* __restrict__ bg0, const float* __restrict__ Wc0,
    float* __restrict__ node0, float* __restrict__ attOut)
{
    __shared__ float sWg0[40], sWc0[200], sWatt[20], sWr1[400];
    __shared__ float sb[3];          // b_att, bg0[0], bg0[1]
    __shared__ float sAcc[40];
    int tid = threadIdx.x;
    for (int i=tid;i<40;i+=NTH)  sWg0[i]=Wg0[i];
    for (int i=tid;i<200;i+=NTH) sWc0[i]=Wc0[i];
    for (int i=tid;i<20;i+=NTH)  sWatt[i]=W_att[i];
    for (int i=tid;i<400;i+=NTH) sWr1[i]=W_r1[i];
    if (tid==0){ sb[0]=b_att[0]; sb[1]=bg0[0]; sb[2]=bg0[1]; }
    if (tid<40) sAcc[tid]=0.f;
    __syncthreads();

    int idx = blockIdx.x*NTH + tid;      // float2 index
    int b = idx >> 13, p = idx & (HW2-1);
    long base = (long)b*Cn*HW2 + p;

    const float2* F0 = (const float2*)f0;
    const float2* H0 = (const float2*)h0;
    const float2* F1 = (const float2*)f1;
    const float2* H1 = (const float2*)h1;
    const float2* H2 = (const float2*)h2;
    float2* N0 = (float2*)node0;
    float2* T1 = (float2*)g_t1;

    // ----- node0 = ConvGRU(x=h0, h=f0) -----
    {
        float2 xv[Cn], hv[Cn];
        #pragma unroll
        for (int c=0;c<Cn;c++){ xv[c]=H0[base+c*HW2]; hv[c]=F0[base+c*HW2]; }
        float g0x=sb[1], g0y=sb[1], g1x=sb[2], g1y=sb[2];
        #pragma unroll
        for (int c=0;c<Cn;c++){
            g0x = fmaf(sWg0[c],    xv[c].x, fmaf(sWg0[10+c], hv[c].x, g0x));
            g0y = fmaf(sWg0[c],    xv[c].y, fmaf(sWg0[10+c], hv[c].y, g0y));
            g1x = fmaf(sWg0[20+c], xv[c].x, fmaf(sWg0[30+c], hv[c].x, g1x));
            g1y = fmaf(sWg0[20+c], xv[c].y, fmaf(sWg0[30+c], hv[c].y, g1y));
        }
        float rx=sigm(g0x), ry=sigm(g0y), ux=sigm(g1x), uy=sigm(g1y);
        #pragma unroll
        for (int o=0;o<Cn;o++){
            float ax=0.f, ay=0.f;
            #pragma unroll
            for (int c=0;c<Cn;c++){
                ax = fmaf(sWc0[o*20+c], xv[c].x, fmaf(sWc0[o*20+10+c], rx*hv[c].x, ax));
                ay = fmaf(sWc0[o*20+c], xv[c].y, fmaf(sWc0[o*20+10+c], ry*hv[c].y, ay));
            }
            float2 r2;
            r2.x = (1.f-ux)*hv[o].x + ux*ftanh(ax);
            r2.y = (1.f-uy)*hv[o].y + uy*ftanh(ay);
            N0[base+o*HW2] = r2;
        }
    }

    // ----- comp_att + t1 + BN1 partials -----
    {
        float2 sv[Cn], fv[Cn];
        float gax=sb[0], gay=sb[0];
        #pragma unroll
        for (int c=0;c<Cn;c++){
            float2 a1v=H1[base+c*HW2], a2v=H2[base+c*HW2];
            gax = fmaf(sWatt[c], a1v.x, fmaf(sWatt[10+c], a2v.x, gax));
            gay = fmaf(sWatt[c], a1v.y, fmaf(sWatt[10+c], a2v.y, gay));
            sv[c].x = a1v.x+a2v.x; sv[c].y = a1v.y+a2v.y;
        }
        float atx = sigm(gax), aty = sigm(gay);
        ((float2*)attOut)[b*HW2+p] = make_float2(atx, aty);
        #pragma unroll
        for (int c=0;c<Cn;c++){
            sv[c].x *= atx; sv[c].y *= aty;
            fv[c] = F1[base+c*HW2];
        }

        int lane = tid & 31;
        long tbase = (long)b*2*Cn*HW2 + p;
        #pragma unroll
        for (int o=0;o<2*Cn;o++){
            float tx=0.f, ty=0.f;
            #pragma unroll
            for (int c=0;c<Cn;c++){
                tx = fmaf(sWr1[o*20+c], fv[c].x, fmaf(sWr1[o*20+10+c], sv[c].x, tx));
                ty = fmaf(sWr1[o*20+c], fv[c].y, fmaf(sWr1[o*20+10+c], sv[c].y, ty));
            }
            T1[tbase + o*HW2] = make_float2(tx, ty);
            float s = tx+ty, q = fmaf(tx,tx, ty*ty);
            #pragma unroll
            for (int off=16;off;off>>=1){
                s += __shfl_xor_sync(0xffffffffu,s,off);
                q += __shfl_xor_sync(0xffffffffu,q,off);
            }
            if (lane==0){ atomicAdd(&sAcc[o],s); atomicAdd(&sAcc[20+o],q); }
        }
    }
    __syncthreads();
    if (tid<40) g_part1[tid*NBL + blockIdx.x] = sAcc[tid];
}

// stats1: one block (32 threads) per channel; sums 512 partials for S and Q
__global__ void k_stats1(const float* __restrict__ gamma, const float* __restrict__ beta){
    int ch = blockIdx.x, lane = threadIdx.x;
    double s=0.0, q=0.0;
    #pragma unroll
    for (int k=0;k<NBL/32;k++){
        s += (double)g_part1[ch*NBL + lane + k*32];
        q += (double)g_part1[(20+ch)*NBL + lane + k*32];
    }
    #pragma unroll
    for (int off=16;off;off>>=1){
        s += __shfl_xor_sync(0xffffffffu,s,off);
        q += __shfl_xor_sync(0xffffffffu,q,off);
    }
    if (lane==0){
        double m = s * (1.0/131072.0);
        double v = q * (1.0/131072.0) - m*m;
        float a = gamma[ch] * rsqrtf((float)v + 1e-5f);
        g_p1[ch]    = a;
        g_p1[20+ch] = beta[ch] - (float)(a*m);
    }
}

// Pass B: x1 = relu(bn1(t1)), y2 = W_r2 @ x1, BN2 block partials
__global__ void __launch_bounds__(NTH) k_passB(const float* __restrict__ W_r2)
{
    __shared__ float sW[200], sP[40], sAcc[20];
    int tid = threadIdx.x;
    for (int i=tid;i<200;i+=NTH) sW[i]=W_r2[i];
    if (tid<40) sP[tid]=g_p1[tid];
    if (tid<20) sAcc[tid]=0.f;
    __syncthreads();

    int idx = blockIdx.x*NTH + tid;
    int b = idx >> 13, p = idx & (HW2-1);
    const float2* T1 = (const float2*)g_t1;
    float2* Y2 = (float2*)g_y2;

    float2 y[Cn];
    #pragma unroll
    for (int o=0;o<Cn;o++) y[o] = make_float2(0.f,0.f);

    long tbase = (long)b*2*Cn*HW2 + p;
    #pragma unroll
    for (int c=0;c<2*Cn;c++){
        float2 t = T1[tbase + c*HW2];
        float ax = fmaxf(fmaf(sP[c], t.x, sP[20+c]), 0.f);
        float ay = fmaxf(fmaf(sP[c], t.y, sP[20+c]), 0.f);
        #pragma unroll
        for (int o=0;o<Cn;o++){
            y[o].x = fmaf(sW[o*20+c], ax, y[o].x);
            y[o].y = fmaf(sW[o*20+c], ay, y[o].y);
        }
    }
    int lane = tid & 31;
    long ybase = (long)b*Cn*HW2 + p;
    #pragma unroll
    for (int o=0;o<Cn;o++){
        Y2[ybase + o*HW2] = y[o];
        float s = y[o].x + y[o].y, q = fmaf(y[o].x,y[o].x, y[o].y*y[o].y);
        #pragma unroll
        for (int off=16;off;off>>=1){
            s += __shfl_xor_sync(0xffffffffu,s,off);
            q += __shfl_xor_sync(0xffffffffu,q,off);
        }
        if (lane==0){ atomicAdd(&sAcc[o],s); atomicAdd(&sAcc[10+o],q); }
    }
    __syncthreads();
    if (tid<20) g_part2[tid*NBL + blockIdx.x] = sAcc[tid];
}

__global__ void k_stats2(const float* __restrict__ gamma, const float* __restrict__ beta){
    int ch = blockIdx.x, lane = threadIdx.x;
    double s=0.0, q=0.0;
    #pragma unroll
    for (int k=0;k<NBL/32;k++){
        s += (double)g_part2[ch*NBL + lane + k*32];
        q += (double)g_part2[(10+ch)*NBL + lane + k*32];
    }
    #pragma unroll
    for (int off=16;off;off>>=1){
        s += __shfl_xor_sync(0xffffffffu,s,off);
        q += __shfl_xor_sync(0xffffffffu,q,off);
    }
    if (lane==0){
        double m = s * (1.0/131072.0);
        double v = q * (1.0/131072.0) - m*m;
        float a = gamma[ch] * rsqrtf((float)v + 1e-5f);
        g_p2[ch]    = a;
        g_p2[10+ch] = beta[ch] - (float)(a*m);
    }
}

// Pass C: comp_full = relu(bn2(y2)), node1 = ConvGRU(x=comp_full, h=f1)
__global__ void __launch_bounds__(NTH) k_passC(
    const float* __restrict__ f1,
    const float* __restrict__ Wg1, const float* __restrict__ bg1, const float* __restrict__ Wc1,
    float* __restrict__ node1)
{
    __shared__ float sWg[40], sWc[200], sP[20], sbg[2];
    int tid = threadIdx.x;
    for (int i=tid;i<40;i+=NTH)  sWg[i]=Wg1[i];
    for (int i=tid;i<200;i+=NTH) sWc[i]=Wc1[i];
    if (tid<20) sP[tid]=g_p2[tid];
    if (tid==0){ sbg[0]=bg1[0]; sbg[1]=bg1[1]; }
    __syncthreads();

    int idx = blockIdx.x*NTH + tid;
    int b = idx >> 13, p = idx & (HW2-1);
    long base = (long)b*Cn*HW2 + p;

    const float2* F1 = (const float2*)f1;
    const float2* Y2 = (const float2*)g_y2;
    float2* N1 = (float2*)node1;

    float2 cf[Cn], fv[Cn];
    #pragma unroll
    for (int o=0;o<Cn;o++){
        float2 yv = Y2[base + o*HW2];
        cf[o].x = fmaxf(fmaf(sP[o], yv.x, sP[10+o]), 0.f);
        cf[o].y = fmaxf(fmaf(sP[o], yv.y, sP[10+o]), 0.f);
        fv[o] = F1[base + o*HW2];
    }

    float g0x=sbg[0], g0y=sbg[0], g1x=sbg[1], g1y=sbg[1];
    #pragma unroll
    for (int c=0;c<Cn;c++){
        g0x = fmaf(sWg[c],    cf[c].x, fmaf(sWg[10+c], fv[c].x, g0x));
        g0y = fmaf(sWg[c],    cf[c].y, fmaf(sWg[10+c], fv[c].y, g0y));
        g1x = fmaf(sWg[20+c], cf[c].x, fmaf(sWg[30+c], fv[c].x, g1x));
        g1y = fmaf(sWg[20+c], cf[c].y, fmaf(sWg[30+c], fv[c].y, g1y));
    }
    float rx=sigm(g0x), ry=sigm(g0y), ux=sigm(g1x), uy=sigm(g1y);
    #pragma unroll
    for (int o=0;o<Cn;o++){
        float ax=0.f, ay=0.f;
        #pragma unroll
        for (int c=0;c<Cn;c++){
            ax = fmaf(sWc[o*20+c], cf[c].x, fmaf(sWc[o*20+10+c], rx*fv[c].x, ax));
            ay = fmaf(sWc[o*20+c], cf[c].y, fmaf(sWc[o*20+10+c], ry*fv[c].y, ay));
        }
        float2 r2;
        r2.x = (1.f-ux)*fv[o].x + ux*ftanh(ax);
        r2.y = (1.f-uy)*fv[o].y + uy*ftanh(ay);
        N1[base + o*HW2] = r2;
    }
}

extern "C" void kernel_launch(void* const* d_in, const int* in_sizes, int n_in,
                              void* d_out, int out_size)
{
    const float* f0    = (const float*)d_in[0];
    const float* f1    = (const float*)d_in[1];
    const float* h0    = (const float*)d_in[2];
    const float* h1    = (const float*)d_in[3];
    const float* h2    = (const float*)d_in[4];
    const float* W_att = (const float*)d_in[5];
    const float* b_att = (const float*)d_in[6];
    const float* W_r1  = (const float*)d_in[7];
    const float* g_r1  = (const float*)d_in[8];
    const float* be_r1 = (const float*)d_in[9];
    const float* W_r2  = (const float*)d_in[10];
    const float* g_r2  = (const float*)d_in[11];
    const float* be_r2 = (const float*)d_in[12];
    const float* Wg0   = (const float*)d_in[13];
    const float* bg0   = (const float*)d_in[14];
    const float* Wc0   = (const float*)d_in[15];
    const float* Wg1   = (const float*)d_in[16];
    const float* bg1   = (const float*)d_in[17];
    const float* Wc1   = (const float*)d_in[18];

    float* out   = (float*)d_out;
    float* node0 = out;                      // [8,10,128,128]
    float* node1 = out + Bn*Cn*HW;           // [8,10,128,128]
    float* att   = out + 2*Bn*Cn*HW;         // [8,1,128,128]

    k_passA<<<NBL, NTH>>>(f0, h0, f1, h1, h2, W_att, b_att, W_r1,
                          Wg0, bg0, Wc0, node0, att);
    k_stats1<<<20, 32>>>(g_r1, be_r1);
    k_passB<<<NBL, NTH>>>(W_r2);
    k_stats2<<<10, 32>>>(g_r2, be_r2);
    k_passC<<<NBL, NTH>>>(f1, Wg1, bg1, Wc1, node1);
}